// round 4
// baseline (speedup 1.0000x reference)
#include <cuda_runtime.h>

#define MAX_N 100000
#define MAX_E 1000000
#define D_FEAT 64
#define N_ETYPES 8
#define EPS_V 1e-8f

// Scratch (static __device__ globals — zero-initialized at module load; the
// kernel restores the counters to 0 before exiting, so every graph replay
// starts from the same state).
__device__ float         g_nw_exp[MAX_N];
__device__ float         g_sum[MAX_N];
__device__ unsigned char g_mask[MAX_N];
__device__ float         g_ft[MAX_N * D_FEAT];
__device__ float         g_ew[N_ETYPES];
__device__ int           g_zero_count;   // # of all-zero feature rows
__device__ int           g_done;         // block arrival counter

// ---------------------------------------------------------------------------
// Single fused kernel.
//  Phase 1 (all blocks): node pass — 16 lanes per node, float4 per lane.
//    For nonzero nodes the output is exactly feat (written immediately).
//    Stores nw_exp / mask for the rare path; block 0 builds the ew table.
//  Phase 2 (last block to arrive only): if any all-zero node exists, run the
//    full edge scatter + finalize with this one block (rare, correctness-only
//    path); then reset the counters.
// ---------------------------------------------------------------------------
__global__ void __launch_bounds__(256) k_all(
    const float4* __restrict__ feat4,            // [N*16]
    const float4* __restrict__ attn4,            // [16]
    const float*  __restrict__ edge_weight,      // [T,T]
    const float*  __restrict__ edge_weight_param,// [T,1]
    const int*    __restrict__ src,
    const int*    __restrict__ dst,
    const int*    __restrict__ e_feat,
    float4*       __restrict__ out4,             // [N*16]
    int N, int E)
{
    // ---------------- Phase 1: node pass ----------------
    const int tid = blockIdx.x * blockDim.x + threadIdx.x;
    const int n   = tid >> 4;           // 16 threads per node
    const int sub = threadIdx.x & 15;

    if (n < N) {
        const float4 f = feat4[(size_t)n * 16 + sub];
        const float4 a = __ldg(attn4 + sub);

        float s_abs = fabsf(f.x) + fabsf(f.y) + fabsf(f.z) + fabsf(f.w);
        float s_dot = f.x * a.x + f.y * a.y + f.z * a.z + f.w * a.w;

        #pragma unroll
        for (int off = 8; off > 0; off >>= 1) {
            s_abs += __shfl_xor_sync(0xFFFFFFFFu, s_abs, off);
            s_dot += __shfl_xor_sync(0xFFFFFFFFu, s_dot, off);
        }

        const bool zero_node = (s_abs == 0.0f);

        if (sub == 0) {
            g_mask[n]   = zero_node ? 0 : 1;
            g_nw_exp[n] = zero_node ? 0.0f : expf(s_dot);   // TEMPERATURE==1
            if (zero_node) atomicAdd(&g_zero_count, 1);
        }

        if (!zero_node) {
            out4[(size_t)n * 16 + sub] = f;                  // out == feat
        } else {
            reinterpret_cast<float4*>(g_ft)[(size_t)n * 16 + sub] =
                make_float4(0.f, 0.f, 0.f, 0.f);
        }
    }

    // Block 0 also builds the per-edge-type weight table (consumed only by
    // the last-arriving block, which is ordered after this via the fence +
    // arrival counter).
    if (blockIdx.x == 0 && threadIdx.x < N_ETYPES) {
        float acc = 0.f;
        #pragma unroll
        for (int j = 0; j < N_ETYPES; ++j)
            acc += edge_weight[threadIdx.x * N_ETYPES + j] * edge_weight_param[j];
        g_ew[threadIdx.x] = acc + 1.0f;
    }

    // ---------------- Arrival: elect the last block ----------------
    __threadfence();          // publish mask/nw_exp/ew before arrival
    __syncthreads();
    __shared__ int s_last;
    if (threadIdx.x == 0)
        s_last = (atomicAdd(&g_done, 1) == gridDim.x - 1) ? 1 : 0;
    __syncthreads();
    if (!s_last) return;

    // ---------------- Phase 2: last block only ----------------
    __threadfence();          // acquire other blocks' writes
    const int zc = g_zero_count;

    if (zc != 0) {            // rare path: some all-zero feature rows exist
        // zero the normalizer accumulators
        for (int i = threadIdx.x; i < N; i += blockDim.x) g_sum[i] = 0.0f;
        __syncthreads();

        // edge scatter
        for (int e = threadIdx.x; e < E; e += blockDim.x) {
            const int s = src[e];
            const int d = dst[e];
            const float w = g_nw_exp[s];
            if (g_mask[d] == 0) {
                atomicAdd(&g_sum[d], w);
                if (w != 0.0f) {
                    const float sc = w * g_ew[e_feat[e] - 1];
                    const float* fs = (const float*)feat4 + (size_t)s * D_FEAT;
                    float* fd = g_ft + (size_t)d * D_FEAT;
                    #pragma unroll
                    for (int k = 0; k < D_FEAT; ++k)
                        atomicAdd(fd + k, fs[k] * sc);
                }
            }
        }
        __syncthreads();

        // finalize zero-mask nodes
        for (int idx = threadIdx.x; idx < N * 16; idx += blockDim.x) {
            const int nn = idx >> 4;
            if (g_mask[nn] != 0) continue;
            const int ss = idx & 15;
            const float sum = g_sum[nn];
            const float inv = 1.0f / ((sum < EPS_V) ? 1.0f : sum);
            const float4 v = reinterpret_cast<const float4*>(g_ft)[(size_t)nn * 16 + ss];
            out4[(size_t)nn * 16 + ss] =
                make_float4(v.x * inv, v.y * inv, v.z * inv, v.w * inv);
        }
        __syncthreads();
    }

    // restore launch-entry invariant for the next graph replay
    if (threadIdx.x == 0) {
        g_zero_count = 0;
        g_done = 0;
    }
}

// ---------------------------------------------------------------------------
extern "C" void kernel_launch(void* const* d_in, const int* in_sizes, int n_in,
                              void* d_out, int out_size)
{
    const float* feat              = (const float*)d_in[0];
    const float* attn              = (const float*)d_in[1];
    const float* edge_weight       = (const float*)d_in[2];
    const float* edge_weight_param = (const float*)d_in[3];
    const int*   src               = (const int*)d_in[4];
    const int*   dst               = (const int*)d_in[5];
    const int*   e_feat            = (const int*)d_in[6];
    float*       out               = (float*)d_out;

    const int N = in_sizes[0] / D_FEAT;   // 100000
    const int E = in_sizes[4];            // 1000000

    const int threads = 256;              // 16 nodes per block
    const int grid = (N * 16 + threads - 1) / threads;   // 6250

    k_all<<<grid, threads>>>((const float4*)feat, (const float4*)attn,
                             edge_weight, edge_weight_param,
                             src, dst, e_feat,
                             (float4*)out, N, E);
}

// round 5
// speedup vs baseline: 1.3104x; 1.3104x over previous
#include <cuda_runtime.h>

#define MAX_N 100000
#define MAX_E 1000000
#define D_FEAT 64
#define N_ETYPES 8
#define EPS_V 1e-8f

// Scratch — static __device__ globals (no runtime allocation). All counters
// are 0 at module load and are restored to 0 by whichever path uses them, so
// every graph replay starts from identical state.
__device__ float         g_nw_exp[MAX_N];
__device__ float         g_sum[MAX_N];
__device__ unsigned char g_mask[MAX_N];
__device__ float         g_ft[MAX_N * D_FEAT];
__device__ float         g_ew[N_ETYPES];
__device__ int           g_zero_count;   // # of all-zero feature rows
__device__ volatile int  g_done;         // rare-path arrival counter (phase 1)
__device__ int           g_done2;        // rare-path arrival counter (phase 2)

// ---------------------------------------------------------------------------
// Kernel 1: node pass — 16 lanes per node, float4 per lane. Streaming.
// No cross-block sync of any kind. Block 0 also builds the ew table (its
// consumer, k_rest, is ordered behind the kernel boundary).
// ---------------------------------------------------------------------------
__global__ void __launch_bounds__(512) k_node(
    const float4* __restrict__ feat4,             // [N*16]
    const float4* __restrict__ attn4,             // [16]
    const float*  __restrict__ edge_weight,       // [T,T]
    const float*  __restrict__ edge_weight_param, // [T,1]
    float4*       __restrict__ out4,              // [N*16]
    int N)
{
    const int tid = blockIdx.x * blockDim.x + threadIdx.x;
    const int n   = tid >> 4;           // 16 threads per node
    const int sub = threadIdx.x & 15;

    if (n < N) {
        const float4 f = __ldcs(feat4 + (size_t)n * 16 + sub);  // evict-first
        const float4 a = __ldg(attn4 + sub);

        float s_abs = fabsf(f.x) + fabsf(f.y) + fabsf(f.z) + fabsf(f.w);
        float s_dot = f.x * a.x + f.y * a.y + f.z * a.z + f.w * a.w;

        #pragma unroll
        for (int off = 8; off > 0; off >>= 1) {
            s_abs += __shfl_xor_sync(0xFFFFFFFFu, s_abs, off);
            s_dot += __shfl_xor_sync(0xFFFFFFFFu, s_dot, off);
        }

        const bool zero_node = (s_abs == 0.0f);

        if (sub == 0) {
            g_mask[n]   = zero_node ? 0 : 1;
            g_nw_exp[n] = zero_node ? 0.0f : expf(s_dot);   // TEMPERATURE==1
            g_sum[n]    = 0.0f;
            if (zero_node) atomicAdd(&g_zero_count, 1);
        }

        if (!zero_node) {
            __stcs(out4 + (size_t)n * 16 + sub, f);          // out == feat
        } else {
            reinterpret_cast<float4*>(g_ft)[(size_t)n * 16 + sub] =
                make_float4(0.f, 0.f, 0.f, 0.f);
        }
    }

    if (blockIdx.x == 0 && threadIdx.x < N_ETYPES) {
        float acc = 0.f;
        #pragma unroll
        for (int j = 0; j < N_ETYPES; ++j)
            acc += edge_weight[threadIdx.x * N_ETYPES + j] * edge_weight_param[j];
        g_ew[threadIdx.x] = acc + 1.0f;
    }
}

// ---------------------------------------------------------------------------
// Kernel 2: rare path only. grid = 148 (one wave, all blocks co-resident so
// the spin barrier is deadlock-free). Common path: one load, exit.
// ---------------------------------------------------------------------------
__global__ void __launch_bounds__(256) k_rest(
    const float* __restrict__ feat,
    const int*   __restrict__ src,
    const int*   __restrict__ dst,
    const int*   __restrict__ e_feat,
    float4*      __restrict__ out4,
    int N, int E)
{
    if (g_zero_count == 0) return;   // common path: nothing to do

    // ---- Rare path: some all-zero feature rows exist ----
    const int gtid   = blockIdx.x * blockDim.x + threadIdx.x;
    const int stride = gridDim.x * blockDim.x;

    // Edge scatter (g_sum was zeroed by k_node; g_ft rows of zero nodes too).
    for (int e = gtid; e < E; e += stride) {
        const int d = dst[e];
        if (g_mask[d] != 0) continue;
        const int s = src[e];
        const float w = g_nw_exp[s];
        atomicAdd(&g_sum[d], w);
        if (w != 0.0f) {
            const float sc = w * g_ew[e_feat[e] - 1];
            const float* fs = feat + (size_t)s * D_FEAT;
            float* fd = g_ft + (size_t)d * D_FEAT;
            #pragma unroll
            for (int k = 0; k < D_FEAT; ++k)
                atomicAdd(fd + k, fs[k] * sc);
        }
    }

    // Grid-wide barrier: arrival counter + spin (all blocks resident).
    __threadfence();
    __syncthreads();
    if (threadIdx.x == 0) {
        atomicAdd((int*)&g_done, 1);
        while (g_done < gridDim.x) __nanosleep(64);
    }
    __syncthreads();
    __threadfence();   // acquire all scatters

    // Finalize zero-mask nodes: out = ft / denom
    for (int idx = gtid; idx < N * 16; idx += stride) {
        const int nn = idx >> 4;
        if (g_mask[nn] != 0) continue;
        const int ss = idx & 15;
        const float sum = g_sum[nn];
        const float inv = 1.0f / ((sum < EPS_V) ? 1.0f : sum);
        const float4 v = reinterpret_cast<const float4*>(g_ft)[(size_t)nn * 16 + ss];
        out4[(size_t)nn * 16 + ss] =
            make_float4(v.x * inv, v.y * inv, v.z * inv, v.w * inv);
    }

    // Reset counters for the next graph replay (last block to finish).
    __syncthreads();
    if (threadIdx.x == 0) {
        if (atomicAdd(&g_done2, 1) == gridDim.x - 1) {
            g_zero_count = 0;
            g_done2 = 0;
            g_done  = 0;
        }
    }
}

// ---------------------------------------------------------------------------
extern "C" void kernel_launch(void* const* d_in, const int* in_sizes, int n_in,
                              void* d_out, int out_size)
{
    const float* feat              = (const float*)d_in[0];
    const float* attn              = (const float*)d_in[1];
    const float* edge_weight       = (const float*)d_in[2];
    const float* edge_weight_param = (const float*)d_in[3];
    const int*   src               = (const int*)d_in[4];
    const int*   dst               = (const int*)d_in[5];
    const int*   e_feat            = (const int*)d_in[6];
    float*       out               = (float*)d_out;

    const int N = in_sizes[0] / D_FEAT;   // 100000
    const int E = in_sizes[4];            // 1000000

    const int threads_n = 512;            // 32 nodes per block
    const int grid_n = (N * 16 + threads_n - 1) / threads_n;   // 3125
    k_node<<<grid_n, threads_n>>>((const float4*)feat, (const float4*)attn,
                                  edge_weight, edge_weight_param,
                                  (float4*)out, N);

    // One wave; common path is a single broadcast load per block.
    k_rest<<<148, 256>>>(feat, src, dst, e_feat, (float4*)out, N, E);
}